// round 9
// baseline (speedup 1.0000x reference)
#include <cuda_runtime.h>
#include <cuda_bf16.h>

// Fused SSIM, R5b (resubmit after infra failure): warp-private strips (64 px),
// no block barriers in the main loop, 8-slot row ring with 4-row load-ahead,
// 4 conv quantities (a, c, ac, a^2+c^2) in float4, even/odd deinterleaved smem,
// 2 px/thread, register vertical ring with multiply-overwrite recycling,
// in-kernel final reduction via self-resetting atomicInc ticket.

#define IMG_W 512
#define IMG_H 512
#define PLANE_STRIDE (512*512)
#define NTHR 128
#define NBLOCKS 384          // 48 planes * 2 * 4; each CTA = 4 independent warps
#define NSTEPS 138
#define C1_CONST 0.0001f
#define C2_CONST 0.0009f

#define W0 0.00102838f
#define W1 0.00759876f
#define W2 0.03600077f
#define W3 0.10936080f
#define W4 0.21300555f
#define W5 0.26601174f

__device__ float    g_partial[NBLOCKS];
__device__ unsigned g_cnt = 0;

__device__ __forceinline__ float gwt(int k) {
    switch (k) {
        case 0: case 10: return W0;
        case 1: case 9:  return W1;
        case 2: case 8:  return W2;
        case 3: case 7:  return W3;
        case 4: case 6:  return W4;
        default:         return W5;
    }
}

__device__ __forceinline__ void f4fma(float4 &a, const float4 v, const float w) {
    a.x = fmaf(v.x, w, a.x);
    a.y = fmaf(v.y, w, a.y);
    a.z = fmaf(v.z, w, a.z);
    a.w = fmaf(v.w, w, a.w);
}
__device__ __forceinline__ float4 f4scale(const float4 v, const float w) {
    return make_float4(v.x * w, v.y * w, v.z * w, v.w * w);
}

__global__ void __launch_bounds__(NTHR, 3)
ssim_kernel(const float* __restrict__ img1, const float* __restrict__ img2,
            float* __restrict__ out) {
    // per-warp slabs: 8-row ring, even/odd deinterleaved float4 quantities
    __shared__ float4 EvS[4][8][40];
    __shared__ float4 OdS[4][8][40];
    __shared__ float  wsum[4];
    __shared__ int    s_last;

    const int t = threadIdx.x;
    const int w = t >> 5;
    const int l = t & 31;
    const int b = blockIdx.x;
    const int plane = b >> 3;                 // 48 planes
    const int ys = (b >> 1) & 3;              // 4 row bands
    const int xs = (b & 1) * 4 + w;           // 8 x-strips, 4 per CTA
    const int x0 = xs * 64;
    const int y0 = ys * 128;

    const float* p1 = img1 + (size_t)plane * PLANE_STRIDE;
    const float* p2 = img2 + (size_t)plane * PLANE_STRIDE;

    float4 (*Ev)[40] = EvS[w];
    float4 (*Od)[40] = OdS[w];

    // vertical scatter rings for output columns 2l and 2l+1 (relative to x0)
    float4 accA[11], accB[11];
#pragma unroll
    for (int j = 0; j < 11; ++j) {
        accA[j] = make_float4(0.f, 0.f, 0.f, 0.f);
        accB[j] = make_float4(0.f, 0.f, 0.f, 0.f);
    }
    float lsum = 0.f;

    // branch-free row loader; callers guarantee step < NSTEPS or clamp
    auto load_row = [&](int step) {
        const int slot = step & 7;
        const int r    = y0 - 5 + step;
        const bool rok = ((unsigned)r < (unsigned)IMG_H) && (step < NSTEPS);
        const float* q1 = p1 + (size_t)(rok ? r : 0) * IMG_W;
        const float* q2 = p2 + (size_t)(rok ? r : 0) * IMG_W;
        {
            const int gx = x0 - 6 + 2 * l;           // even px = 2l-6 (rel)
            const bool k0 = rok && ((unsigned)gx       < (unsigned)IMG_W);
            const bool k1 = rok && ((unsigned)(gx + 1) < (unsigned)IMG_W);
            const float a0 = k0 ? __ldg(q1 + gx)     : 0.f;
            const float c0 = k0 ? __ldg(q2 + gx)     : 0.f;
            const float a1 = k1 ? __ldg(q1 + gx + 1) : 0.f;
            const float c1 = k1 ? __ldg(q2 + gx + 1) : 0.f;
            Ev[slot][l] = make_float4(a0, c0, a0 * c0, fmaf(a0, a0, c0 * c0));
            Od[slot][l] = make_float4(a1, c1, a1 * c1, fmaf(a1, a1, c1 * c1));
        }
        if (l < 6) {                                 // tail px 58..69 (rel)
            const int gx = x0 + 58 + 2 * l;
            const bool k0 = rok && (gx     < IMG_W);
            const bool k1 = rok && (gx + 1 < IMG_W);
            const float a0 = k0 ? __ldg(q1 + gx)     : 0.f;
            const float c0 = k0 ? __ldg(q2 + gx)     : 0.f;
            const float a1 = k1 ? __ldg(q1 + gx + 1) : 0.f;
            const float c1 = k1 ? __ldg(q2 + gx + 1) : 0.f;
            Ev[slot][32 + l] = make_float4(a0, c0, a0 * c0, fmaf(a0, a0, c0 * c0));
            Od[slot][32 + l] = make_float4(a1, c1, a1 * c1, fmaf(a1, a1, c1 * c1));
        }
    };

    auto epi = [&](const float4 q) {   // q = (mu1, mu2, e12, e11+e22)
        const float m11 = q.x * q.x;
        const float m22 = q.y * q.y;
        const float m12 = q.x * q.y;
        const float num = (2.f * m12 + C1_CONST) * (2.f * (q.z - m12) + C2_CONST);
        const float den = (m11 + m22 + C1_CONST) * ((q.w - m11 - m22) + C2_CONST);
        lsum += __fdividef(num, den);
    };

#define PROC(SV, RR) {                                                         \
    const int sl_ = (SV) & 7;                                                  \
    const float4* ev = Ev[sl_];                                                \
    const float4* od = Od[sl_];                                                \
    float4 hA = make_float4(0.f, 0.f, 0.f, 0.f);                               \
    float4 hB = make_float4(0.f, 0.f, 0.f, 0.f);                               \
    float4 v_;                                                                 \
    v_ = od[l];     f4fma(hA, v_, W0);                                         \
    v_ = ev[l + 1]; f4fma(hA, v_, W1); f4fma(hB, v_, W0);                      \
    v_ = od[l + 1]; f4fma(hA, v_, W2); f4fma(hB, v_, W1);                      \
    v_ = ev[l + 2]; f4fma(hA, v_, W3); f4fma(hB, v_, W2);                      \
    v_ = od[l + 2]; f4fma(hA, v_, W4); f4fma(hB, v_, W3);                      \
    v_ = ev[l + 3]; f4fma(hA, v_, W5); f4fma(hB, v_, W4);                      \
    v_ = od[l + 3]; f4fma(hA, v_, W4); f4fma(hB, v_, W5);                      \
    v_ = ev[l + 4]; f4fma(hA, v_, W3); f4fma(hB, v_, W4);                      \
    v_ = od[l + 4]; f4fma(hA, v_, W2); f4fma(hB, v_, W3);                      \
    v_ = ev[l + 5]; f4fma(hA, v_, W1); f4fma(hB, v_, W2);                      \
    v_ = od[l + 5]; f4fma(hA, v_, W0); f4fma(hB, v_, W1);                      \
    v_ = ev[l + 6];                    f4fma(hB, v_, W0);                      \
    _Pragma("unroll")                                                          \
    for (int j = 0; j < 10; ++j) {                                             \
        const float wj = gwt(j);                                               \
        const int sl = ((RR) + j) % 11;                                        \
        f4fma(accA[sl], hA, wj);                                               \
        f4fma(accB[sl], hB, wj);                                               \
    }                                                                          \
    {   /* j=10: first tap of freshly recycled slot -> overwrite */            \
        const int sl = ((RR) + 10) % 11;                                       \
        accA[sl] = f4scale(hA, W0);                                            \
        accB[sl] = f4scale(hB, W0);                                            \
    }                                                                          \
    if ((SV) >= 10) { epi(accA[RR]); epi(accB[RR]); }                          \
}

    load_row(0); load_row(1); load_row(2); load_row(3);

    int s = 0;
#pragma unroll 1
    for (int blk = 0; blk < 6; ++blk) {          // 6 * 22 = 132 rows
#pragma unroll
        for (int it = 0; it < 11; ++it) {
            load_row(s + 4);
            load_row(s + 5);
            __syncwarp();
            PROC(s,     (2 * it) % 11);
            PROC(s + 1, (2 * it + 1) % 11);
            s += 2;
        }
    }
#pragma unroll
    for (int it = 0; it < 3; ++it) {             // rows 132..137 (132 % 11 == 0)
        load_row(s + 4);
        load_row(s + 5);
        __syncwarp();
        PROC(s,     2 * it);
        PROC(s + 1, 2 * it + 1);
        s += 2;
    }
#undef PROC

    // deterministic per-CTA partial
    float v = lsum;
#pragma unroll
    for (int o = 16; o; o >>= 1) v += __shfl_xor_sync(0xffffffffu, v, o);
    if (l == 0) wsum[w] = v;
    __syncthreads();
    if (t == 0) {
        g_partial[b] = (wsum[0] + wsum[1]) + (wsum[2] + wsum[3]);
        __threadfence();
        // atomicInc wraps to 0 at NBLOCKS-1: self-resetting across launches,
        // robust even if a previous run was aborted mid-flight.
        const unsigned tk = atomicInc(&g_cnt, NBLOCKS - 1);
        s_last = (tk == NBLOCKS - 1);
    }
    __syncthreads();

    // last CTA: deterministic final reduction
    if (s_last) {
        float sv = __ldcg(&g_partial[t]) + __ldcg(&g_partial[t + 128]) +
                   __ldcg(&g_partial[t + 256]);
#pragma unroll
        for (int o = 16; o; o >>= 1) sv += __shfl_xor_sync(0xffffffffu, sv, o);
        if (l == 0) wsum[w] = sv;
        __syncthreads();
        if (t == 0) {
            out[0] = ((wsum[0] + wsum[1]) + (wsum[2] + wsum[3])) *
                     (1.0f / 12582912.0f);
        }
    }
}

extern "C" void kernel_launch(void* const* d_in, const int* in_sizes, int n_in,
                              void* d_out, int out_size) {
    const float* img1 = (const float*)d_in[0];
    const float* img2 = (const float*)d_in[1];
    (void)in_sizes; (void)n_in; (void)out_size;
    ssim_kernel<<<NBLOCKS, NTHR>>>(img1, img2, (float*)d_out);
}

// round 11
// speedup vs baseline: 1.4349x; 1.4349x over previous
#include <cuda_runtime.h>
#include <cuda_bf16.h>

// Fused SSIM, R6: R4 trunk (256-wide strips, 4 warps, block barriers, float4
// quantities (a, c, ac, a^2+c^2), even/odd deinterleave, 2 px/thread, register
// vertical ring) + split loader (LDG early into regs, STS after compute) so
// gmem latency hides behind the PROC FMA chains + in-kernel ticket reduction.

#define IMG_W 512
#define IMG_H 512
#define PLANE_STRIDE (512*512)
#define NTHR 128
#define NBLOCKS 384          // 48 planes * 2 x-strips * 4 y-bands
#define NSTEPS 138
#define C1_CONST 0.0001f
#define C2_CONST 0.0009f

#define W0 0.00102838f
#define W1 0.00759876f
#define W2 0.03600077f
#define W3 0.10936080f
#define W4 0.21300555f
#define W5 0.26601174f

__device__ float    g_partial[NBLOCKS];
__device__ unsigned g_cnt = 0;

__device__ __forceinline__ float gwt(int k) {
    switch (k) {
        case 0: case 10: return W0;
        case 1: case 9:  return W1;
        case 2: case 8:  return W2;
        case 3: case 7:  return W3;
        case 4: case 6:  return W4;
        default:         return W5;
    }
}

__device__ __forceinline__ void f4fma(float4 &a, const float4 v, const float w) {
    a.x = fmaf(v.x, w, a.x);
    a.y = fmaf(v.y, w, a.y);
    a.z = fmaf(v.z, w, a.z);
    a.w = fmaf(v.w, w, a.w);
}
__device__ __forceinline__ float4 f4scale(const float4 v, const float w) {
    return make_float4(v.x * w, v.y * w, v.z * w, v.w * w);
}

struct RowRegs { float a0, c0, a1, c1, ta0, tc0, ta1, tc1; };

__global__ void __launch_bounds__(NTHR, 3)
ssim_kernel(const float* __restrict__ img1, const float* __restrict__ img2,
            float* __restrict__ out) {
    __shared__ float4 Ev[4][136];
    __shared__ float4 Od[4][136];
    __shared__ float  wsum[4];
    __shared__ int    s_last;

    const int t  = threadIdx.x;
    const int w  = t >> 5;
    const int l  = t & 31;
    const int b  = blockIdx.x;
    const int plane = b >> 3;
    const int x0 = (b & 1) * 256;
    const int y0 = ((b >> 1) & 3) * 128;

    const float* p1 = img1 + (size_t)plane * PLANE_STRIDE;
    const float* p2 = img2 + (size_t)plane * PLANE_STRIDE;

    float4 accA[11], accB[11];
#pragma unroll
    for (int j = 0; j < 11; ++j) {
        accA[j] = make_float4(0.f, 0.f, 0.f, 0.f);
        accB[j] = make_float4(0.f, 0.f, 0.f, 0.f);
    }
    float lsum = 0.f;

    // LDG phase: raw values into registers (zero outside image / past NSTEPS)
    auto ldg_row = [&](int step, RowRegs &R) {
        const int r    = y0 - 5 + step;
        const bool rok = ((unsigned)r < (unsigned)IMG_H) && (step < NSTEPS);
        const float* q1 = p1 + (size_t)(rok ? r : 0) * IMG_W;
        const float* q2 = p2 + (size_t)(rok ? r : 0) * IMG_W;
        const int gx = x0 - 6 + 2 * t;
        const bool k0 = rok && ((unsigned)gx       < (unsigned)IMG_W);
        const bool k1 = rok && ((unsigned)(gx + 1) < (unsigned)IMG_W);
        R.a0 = k0 ? __ldg(q1 + gx)     : 0.f;
        R.c0 = k0 ? __ldg(q2 + gx)     : 0.f;
        R.a1 = k1 ? __ldg(q1 + gx + 1) : 0.f;
        R.c1 = k1 ? __ldg(q2 + gx + 1) : 0.f;
        R.ta0 = R.tc0 = R.ta1 = R.tc1 = 0.f;
        if (t < 6) {                       // tail px 250..261 (rel)
            const int g2 = x0 + 250 + 2 * t;
            const bool m0 = rok && (g2     < IMG_W);
            const bool m1 = rok && (g2 + 1 < IMG_W);
            R.ta0 = m0 ? __ldg(q1 + g2)     : 0.f;
            R.tc0 = m0 ? __ldg(q2 + g2)     : 0.f;
            R.ta1 = m1 ? __ldg(q1 + g2 + 1) : 0.f;
            R.tc1 = m1 ? __ldg(q2 + g2 + 1) : 0.f;
        }
    };

    // STS phase: derived quantities into the 4-slot row ring
    auto sts_row = [&](int step, const RowRegs &R) {
        const int slot = step & 3;
        Ev[slot][t] = make_float4(R.a0, R.c0, R.a0 * R.c0,
                                  fmaf(R.a0, R.a0, R.c0 * R.c0));
        Od[slot][t] = make_float4(R.a1, R.c1, R.a1 * R.c1,
                                  fmaf(R.a1, R.a1, R.c1 * R.c1));
        if (t < 6) {
            Ev[slot][128 + t] = make_float4(R.ta0, R.tc0, R.ta0 * R.tc0,
                                            fmaf(R.ta0, R.ta0, R.tc0 * R.tc0));
            Od[slot][128 + t] = make_float4(R.ta1, R.tc1, R.ta1 * R.tc1,
                                            fmaf(R.ta1, R.ta1, R.tc1 * R.tc1));
        }
    };

    auto epi = [&](const float4 q) {   // q = (mu1, mu2, e12, e11+e22)
        const float m11 = q.x * q.x;
        const float m22 = q.y * q.y;
        const float m12 = q.x * q.y;
        const float num = (2.f * m12 + C1_CONST) * (2.f * (q.z - m12) + C2_CONST);
        const float den = (m11 + m22 + C1_CONST) * ((q.w - m11 - m22) + C2_CONST);
        lsum += __fdividef(num, den);
    };

#define PROC(SV, RR) {                                                         \
    const int sl_ = (SV) & 3;                                                  \
    const float4* ev = Ev[sl_];                                                \
    const float4* od = Od[sl_];                                                \
    float4 hA = make_float4(0.f, 0.f, 0.f, 0.f);                               \
    float4 hB = make_float4(0.f, 0.f, 0.f, 0.f);                               \
    float4 v_;                                                                 \
    v_ = od[t];     f4fma(hA, v_, W0);                                         \
    v_ = ev[t + 1]; f4fma(hA, v_, W1); f4fma(hB, v_, W0);                      \
    v_ = od[t + 1]; f4fma(hA, v_, W2); f4fma(hB, v_, W1);                      \
    v_ = ev[t + 2]; f4fma(hA, v_, W3); f4fma(hB, v_, W2);                      \
    v_ = od[t + 2]; f4fma(hA, v_, W4); f4fma(hB, v_, W3);                      \
    v_ = ev[t + 3]; f4fma(hA, v_, W5); f4fma(hB, v_, W4);                      \
    v_ = od[t + 3]; f4fma(hA, v_, W4); f4fma(hB, v_, W5);                      \
    v_ = ev[t + 4]; f4fma(hA, v_, W3); f4fma(hB, v_, W4);                      \
    v_ = od[t + 4]; f4fma(hA, v_, W2); f4fma(hB, v_, W3);                      \
    v_ = ev[t + 5]; f4fma(hA, v_, W1); f4fma(hB, v_, W2);                      \
    v_ = od[t + 5]; f4fma(hA, v_, W0); f4fma(hB, v_, W1);                      \
    v_ = ev[t + 6];                    f4fma(hB, v_, W0);                      \
    _Pragma("unroll")                                                          \
    for (int j = 0; j < 10; ++j) {                                             \
        const float wj = gwt(j);                                               \
        const int sl = ((RR) + j) % 11;                                        \
        f4fma(accA[sl], hA, wj);                                               \
        f4fma(accB[sl], hB, wj);                                               \
    }                                                                          \
    {   /* j=10: first tap of freshly recycled slot -> overwrite */            \
        const int sl = ((RR) + 10) % 11;                                       \
        accA[sl] = f4scale(hA, W0);                                            \
        accB[sl] = f4scale(hB, W0);                                            \
    }                                                                          \
    if ((SV) >= 10) { epi(accA[RR]); epi(accB[RR]); }                          \
}

    // prime slots 0,1
    {
        RowRegs R0, R1;
        ldg_row(0, R0); ldg_row(1, R1);
        sts_row(0, R0); sts_row(1, R1);
        __syncthreads();
    }

    int s = 0;
    RowRegs Ra, Rb;
#pragma unroll 1
    for (int blk = 0; blk < 6; ++blk) {          // 6 * 22 = 132 rows
#pragma unroll
        for (int it = 0; it < 11; ++it) {
            ldg_row(s + 2, Ra);                  // LDG early
            ldg_row(s + 3, Rb);
            PROC(s,     (2 * it) % 11);          // compute covers the latency
            PROC(s + 1, (2 * it + 1) % 11);
            sts_row(s + 2, Ra);                  // STS late
            sts_row(s + 3, Rb);
            __syncthreads();
            s += 2;
        }
    }
#pragma unroll
    for (int it = 0; it < 3; ++it) {             // rows 132..137 (132 % 11 == 0)
        ldg_row(s + 2, Ra);
        ldg_row(s + 3, Rb);
        PROC(s,     2 * it);
        PROC(s + 1, 2 * it + 1);
        sts_row(s + 2, Ra);
        sts_row(s + 3, Rb);
        __syncthreads();
        s += 2;
    }
#undef PROC

    // deterministic per-CTA partial
    float v = lsum;
#pragma unroll
    for (int o = 16; o; o >>= 1) v += __shfl_xor_sync(0xffffffffu, v, o);
    if (l == 0) wsum[w] = v;
    __syncthreads();
    if (t == 0) {
        g_partial[b] = (wsum[0] + wsum[1]) + (wsum[2] + wsum[3]);
        __threadfence();
        const unsigned tk = atomicInc(&g_cnt, NBLOCKS - 1);  // self-resetting
        s_last = (tk == NBLOCKS - 1);
    }
    __syncthreads();

    // last CTA: deterministic final reduction
    if (s_last) {
        float sv = __ldcg(&g_partial[t]) + __ldcg(&g_partial[t + 128]) +
                   __ldcg(&g_partial[t + 256]);
#pragma unroll
        for (int o = 16; o; o >>= 1) sv += __shfl_xor_sync(0xffffffffu, sv, o);
        if (l == 0) wsum[w] = sv;
        __syncthreads();
        if (t == 0) {
            out[0] = ((wsum[0] + wsum[1]) + (wsum[2] + wsum[3])) *
                     (1.0f / 12582912.0f);
        }
    }
}

extern "C" void kernel_launch(void* const* d_in, const int* in_sizes, int n_in,
                              void* d_out, int out_size) {
    const float* img1 = (const float*)d_in[0];
    const float* img2 = (const float*)d_in[1];
    (void)in_sizes; (void)n_in; (void)out_size;
    ssim_kernel<<<NBLOCKS, NTHR>>>(img1, img2, (float*)d_out);
}

// round 12
// speedup vs baseline: 1.6531x; 1.1521x over previous
#include <cuda_runtime.h>
#include <cuda_bf16.h>

// Fused SSIM, R7: quantity-split halves. 256-thread CTAs: threads 0-127 ("P")
// convolve (a, c); threads 128-255 ("Q") convolve (a*c, a^2+c^2) for the same
// 256-wide strip. Vertical register ring shrinks to 11 x float2 x 2px = 44
// regs -> 85-reg cap -> 3 CTAs/SM (24 warps). Halves exchange completed rows
// through a small smem ring and each does half the epilogue divides.
// In-kernel ticket reduction.

#define IMG_W 512
#define IMG_H 512
#define PLANE_STRIDE (512*512)
#define NTHR 256
#define NBLOCKS 384          // 48 planes * 2 x-strips * 4 y-bands (one wave @3/SM)
#define NSTEPS 138
#define C1_CONST 0.0001f
#define C2_CONST 0.0009f

#define W0 0.00102838f
#define W1 0.00759876f
#define W2 0.03600077f
#define W3 0.10936080f
#define W4 0.21300555f
#define W5 0.26601174f

__device__ float    g_partial[NBLOCKS];
__device__ unsigned g_cnt = 0;

__device__ __forceinline__ float gwt(int k) {
    switch (k) {
        case 0: case 10: return W0;
        case 1: case 9:  return W1;
        case 2: case 8:  return W2;
        case 3: case 7:  return W3;
        case 4: case 6:  return W4;
        default:         return W5;
    }
}

__device__ __forceinline__ void f2fma(float2 &a, const float2 v, const float w) {
    a.x = fmaf(v.x, w, a.x);
    a.y = fmaf(v.y, w, a.y);
}
__device__ __forceinline__ float2 f2scale(const float2 v, const float w) {
    return make_float2(v.x * w, v.y * w);
}

__global__ void __launch_bounds__(NTHR, 3)
ssim_kernel(const float* __restrict__ img1, const float* __restrict__ img2,
            float* __restrict__ out) {
    // 4-slot row rings, even/odd deinterleaved, float2 payloads:
    //   Pe/Po: (a, c)   Qe/Qo: (a*c, a^2+c^2)
    __shared__ float2 Pe[4][136], Po[4][136];
    __shared__ float2 Qe[4][136], Qo[4][136];
    // exchange rings: Xm = mu-pairs of odd px (written by P, read by Q)
    //                 Xq = E-pairs  of even px (written by Q, read by P)
    __shared__ float2 Xm[4][128], Xq[4][128];
    __shared__ float  wsum[8];
    __shared__ int    s_last;

    const int  t   = threadIdx.x;
    const int  u   = t & 127;
    const bool isP = (t < 128);
    const int  b   = blockIdx.x;
    const int  plane = b >> 3;
    const int  x0 = (b & 1) * 256;
    const int  y0 = ((b >> 1) & 3) * 128;

    const float* p1 = img1 + (size_t)plane * PLANE_STRIDE;
    const float* p2 = img2 + (size_t)plane * PLANE_STRIDE;

    // per-half runtime views (code below is identical for both halves)
    float2 (* const AE)[136] = isP ? Pe : Qe;   // this half's even array
    float2 (* const AO)[136] = isP ? Po : Qo;   // this half's odd array
    float2 (* const XW)[128] = isP ? Xm : Xq;   // publish to counterpart
    float2 (* const XR)[128] = isP ? Xq : Xm;   // read from counterpart

    // vertical ring: this half's 2 quantities for output px 2u (E) and 2u+1 (O)
    float2 accE[11], accO[11];
#pragma unroll
    for (int j = 0; j < 11; ++j) {
        accE[j] = make_float2(0.f, 0.f);
        accO[j] = make_float2(0.f, 0.f);
    }
    float2 hprev0 = make_float2(0.f, 0.f);
    float2 hprev1 = make_float2(0.f, 0.f);
    float  lsum = 0.f;

    // loader: ONE row per half per stage; writes all four row arrays
    auto load_row = [&](int step) {
        const int  slot = step & 3;
        const int  r    = y0 - 5 + step;
        const bool rok  = ((unsigned)r < (unsigned)IMG_H) && (step < NSTEPS);
        const float* q1 = p1 + (size_t)(rok ? r : 0) * IMG_W;
        const float* q2 = p2 + (size_t)(rok ? r : 0) * IMG_W;
        {
            const int gx = x0 - 6 + 2 * u;          // even px = 2u-6 (rel)
            const bool k0 = rok && ((unsigned)gx       < (unsigned)IMG_W);
            const bool k1 = rok && ((unsigned)(gx + 1) < (unsigned)IMG_W);
            const float a0 = k0 ? __ldg(q1 + gx)     : 0.f;
            const float c0 = k0 ? __ldg(q2 + gx)     : 0.f;
            const float a1 = k1 ? __ldg(q1 + gx + 1) : 0.f;
            const float c1 = k1 ? __ldg(q2 + gx + 1) : 0.f;
            Pe[slot][u] = make_float2(a0, c0);
            Po[slot][u] = make_float2(a1, c1);
            Qe[slot][u] = make_float2(a0 * c0, fmaf(a0, a0, c0 * c0));
            Qo[slot][u] = make_float2(a1 * c1, fmaf(a1, a1, c1 * c1));
        }
        if (u < 6) {                                 // tail px 250..261 (rel)
            const int gx = x0 + 250 + 2 * u;
            const bool k0 = rok && (gx     < IMG_W);
            const bool k1 = rok && (gx + 1 < IMG_W);
            const float a0 = k0 ? __ldg(q1 + gx)     : 0.f;
            const float c0 = k0 ? __ldg(q2 + gx)     : 0.f;
            const float a1 = k1 ? __ldg(q1 + gx + 1) : 0.f;
            const float c1 = k1 ? __ldg(q2 + gx + 1) : 0.f;
            Pe[slot][128 + u] = make_float2(a0, c0);
            Po[slot][128 + u] = make_float2(a1, c1);
            Qe[slot][128 + u] = make_float2(a0 * c0, fmaf(a0, a0, c0 * c0));
            Qo[slot][128 + u] = make_float2(a1 * c1, fmaf(a1, a1, c1 * c1));
        }
    };

    // epilogue: mu = (mu1, mu2), E = (E[ac], E[a^2+c^2])
    auto epi = [&](const float2 mu, const float2 E) {
        const float m11 = mu.x * mu.x;
        const float m22 = mu.y * mu.y;
        const float m12 = mu.x * mu.y;
        const float num = (2.f * m12 + C1_CONST) * (2.f * (E.x - m12) + C2_CONST);
        const float den = (m11 + m22 + C1_CONST) * ((E.y - m11 - m22) + C2_CONST);
        lsum += __fdividef(num, den);
    };

#define PROC(SV, RR, HOLD) {                                                   \
    const int sl_ = (SV) & 3;                                                  \
    const float2* ev = AE[sl_];                                                \
    const float2* od = AO[sl_];                                                \
    float2 hA = make_float2(0.f, 0.f);                                         \
    float2 hB = make_float2(0.f, 0.f);                                         \
    float2 v_;                                                                 \
    v_ = od[u];     f2fma(hA, v_, W0);                                         \
    v_ = ev[u + 1]; f2fma(hA, v_, W1); f2fma(hB, v_, W0);                      \
    v_ = od[u + 1]; f2fma(hA, v_, W2); f2fma(hB, v_, W1);                      \
    v_ = ev[u + 2]; f2fma(hA, v_, W3); f2fma(hB, v_, W2);                      \
    v_ = od[u + 2]; f2fma(hA, v_, W4); f2fma(hB, v_, W3);                      \
    v_ = ev[u + 3]; f2fma(hA, v_, W5); f2fma(hB, v_, W4);                      \
    v_ = od[u + 3]; f2fma(hA, v_, W4); f2fma(hB, v_, W5);                      \
    v_ = ev[u + 4]; f2fma(hA, v_, W3); f2fma(hB, v_, W4);                      \
    v_ = od[u + 4]; f2fma(hA, v_, W2); f2fma(hB, v_, W3);                      \
    v_ = ev[u + 5]; f2fma(hA, v_, W1); f2fma(hB, v_, W2);                      \
    v_ = od[u + 5]; f2fma(hA, v_, W0); f2fma(hB, v_, W1);                      \
    v_ = ev[u + 6];                    f2fma(hB, v_, W0);                      \
    _Pragma("unroll")                                                          \
    for (int j = 0; j < 10; ++j) {                                             \
        const float wj = gwt(j);                                               \
        const int sl = ((RR) + j) % 11;                                        \
        f2fma(accE[sl], hA, wj);                                               \
        f2fma(accO[sl], hB, wj);                                               \
    }                                                                          \
    {   /* j=10: first tap of freshly recycled slot -> overwrite */            \
        const int sl = ((RR) + 10) % 11;                                       \
        accE[sl] = f2scale(hA, W0);                                            \
        accO[sl] = f2scale(hB, W0);                                            \
    }                                                                          \
    {   /* completion of output row (SV)-10: publish + hold */                 \
        const float2 ce = accE[RR];                                            \
        const float2 co = accO[RR];                                            \
        XW[((SV) - 10) & 3][u] = isP ? co : ce;                                \
        HOLD = isP ? ce : co;                                                  \
    }                                                                          \
}

// one pipeline stage: epi of rows s-12/s-11, load one row, PROC rows s, s+1
#define STAGE(SVAL, RRa, RRb) {                                                \
    const int s_ = (SVAL);                                                     \
    if (s_ >= 12) {                                                            \
        const float2 r0 = XR[(s_ - 12) & 3][u];                                \
        const float2 r1 = XR[(s_ - 11) & 3][u];                                \
        if (isP) { epi(hprev0, r0); epi(hprev1, r1); }                         \
        else     { epi(r0, hprev0); epi(r1, hprev1); }                         \
    }                                                                          \
    load_row(s_ + 2 + (isP ? 0 : 1));                                          \
    PROC(s_,     RRa, hprev0);                                                 \
    PROC(s_ + 1, RRb, hprev1);                                                 \
    __syncthreads();                                                           \
}

    // prologue: P loads row 0, Q loads row 1
    load_row(isP ? 0 : 1);
    __syncthreads();

    int s = 0;
#pragma unroll 1
    for (int blk = 0; blk < 6; ++blk) {          // stages s = 0..130 (66 stages)
#pragma unroll
        for (int it = 0; it < 11; ++it) {
            STAGE(s, (2 * it) % 11, (2 * it + 1) % 11);
            s += 2;
        }
    }
#pragma unroll
    for (int it = 0; it < 3; ++it) {             // stages s = 132, 134, 136
        STAGE(s, 2 * it, 2 * it + 1);
        s += 2;
    }
#undef STAGE
#undef PROC

    // drain: epi of the last two output rows (126, 127), completed at s=136
    {
        const float2 r0 = XR[(138 - 12) & 3][u];
        const float2 r1 = XR[(138 - 11) & 3][u];
        if (isP) { epi(hprev0, r0); epi(hprev1, r1); }
        else     { epi(r0, hprev0); epi(r1, hprev1); }
    }

    // deterministic per-CTA partial (8 warps)
    float v = lsum;
#pragma unroll
    for (int o = 16; o; o >>= 1) v += __shfl_xor_sync(0xffffffffu, v, o);
    if ((t & 31) == 0) wsum[t >> 5] = v;
    __syncthreads();
    if (t == 0) {
        g_partial[b] = ((wsum[0] + wsum[1]) + (wsum[2] + wsum[3])) +
                       ((wsum[4] + wsum[5]) + (wsum[6] + wsum[7]));
        __threadfence();
        const unsigned tk = atomicInc(&g_cnt, NBLOCKS - 1);  // self-resetting
        s_last = (tk == NBLOCKS - 1);
    }
    __syncthreads();

    // last CTA: deterministic final reduction over 384 partials
    if (s_last) {
        float sv = __ldcg(&g_partial[t]) +
                   ((t < 128) ? __ldcg(&g_partial[t + 256]) : 0.f);
#pragma unroll
        for (int o = 16; o; o >>= 1) sv += __shfl_xor_sync(0xffffffffu, sv, o);
        if ((t & 31) == 0) wsum[t >> 5] = sv;
        __syncthreads();
        if (t == 0) {
            out[0] = (((wsum[0] + wsum[1]) + (wsum[2] + wsum[3])) +
                      ((wsum[4] + wsum[5]) + (wsum[6] + wsum[7]))) *
                     (1.0f / 12582912.0f);
        }
    }
}

extern "C" void kernel_launch(void* const* d_in, const int* in_sizes, int n_in,
                              void* d_out, int out_size) {
    const float* img1 = (const float*)d_in[0];
    const float* img2 = (const float*)d_in[1];
    (void)in_sizes; (void)n_in; (void)out_size;
    ssim_kernel<<<NBLOCKS, NTHR>>>(img1, img2, (float*)d_out);
}